// round 2
// baseline (speedup 1.0000x reference)
#include <cuda_runtime.h>
#include <cstdint>
#include <math.h>

#define CS     8      // CTAs per batch (row slabs)
#define ROWS   24     // rows per CTA = 192/8
#define PITCH  196    // row pitch in floats: 2 zero cols + 192 data + 2 zero cols
#define LROWS  26     // ROWS + 2 halo rows
#define NG     192
#define TSTEPS 256
#define NTHR   768
#define KPT    6      // rows per thread (4 row-groups of 192 threads)

__device__ __forceinline__ uint32_t s2u(const void* p) {
    return (uint32_t)__cvta_generic_to_shared((void*)p);
}
__device__ __forceinline__ uint32_t mapa_u32(uint32_t a, uint32_t r) {
    uint32_t d;
    asm("mapa.shared::cluster.u32 %0, %1, %2;" : "=r"(d) : "r"(a), "r"(r));
    return d;
}
__device__ __forceinline__ void st_cluster_f32(uint32_t a, float v) {
    asm volatile("st.shared::cluster.f32 [%0], %1;" :: "r"(a), "f"(v) : "memory");
}
__device__ __forceinline__ void cluster_sync_() {
    asm volatile("barrier.cluster.arrive.aligned;" ::: "memory");
    asm volatile("barrier.cluster.wait.aligned;" ::: "memory");
}
__device__ __forceinline__ void mbar_init(uint32_t a, uint32_t cnt) {
    asm volatile("mbarrier.init.shared.b64 [%0], %1;" :: "r"(a), "r"(cnt) : "memory");
}
// Remote arrive on a peer CTA's mbarrier, release at cluster scope.
__device__ __forceinline__ void mbar_arrive_remote(uint32_t remAddr) {
    asm volatile("mbarrier.arrive.release.cluster.shared::cluster.b64 _, [%0];"
                 :: "r"(remAddr) : "memory");
}
// Wait on own mbarrier phase parity, acquire at cluster scope (orders peer DSMEM stores).
__device__ __forceinline__ void mbar_wait_parity_cluster(uint32_t addr, uint32_t parity) {
    asm volatile(
        "{\n\t"
        ".reg .pred P;\n\t"
        "WL_%=:\n\t"
        "mbarrier.try_wait.parity.acquire.cluster.shared::cta.b64 P, [%0], %1, 0x989680;\n\t"
        "@P bra.uni WD_%=;\n\t"
        "bra.uni WL_%=;\n\t"
        "WD_%=:\n\t"
        "}"
        :: "r"(addr), "r"(parity) : "memory");
}

// PML 1D profile: v[k] = 3*(k/20)^4 ; b[i] = v[20-i] for i<=20, v[i-171] for i>=171
__device__ __forceinline__ float pml1(int i) {
    int d;
    if (i <= 20)           d = 20 - i;
    else if (i >= NG - 21) d = i - (NG - 21);
    else return 0.0f;
    double t = (double)d * 0.05;
    double t2 = t * t;
    return (float)(3.0 * t2 * t2);
}

__global__ void __cluster_dims__(CS, 1, 1) __launch_bounds__(NTHR, 1)
wave_kernel(const float* __restrict__ x, const float* __restrict__ rho,
            float* __restrict__ out)
{
    __shared__ float bufs[2][LROWS * PITCH];  // double-buffered y field
    __shared__ float xs[TSTEPS];              // per-batch source series
    __shared__ float pbuf[3];                 // probe accumulators (rank 6 only)
    __shared__ alignas(8) unsigned long long mbar;

    const int tid   = threadIdx.x;
    const int col   = tid % NG;       // 0..191
    const int rgrp  = tid / NG;       // 0..3
    const int rank  = blockIdx.x % CS;
    const int batch = blockIdx.x / CS;

    const int nUp = (rank > 0), nDn = (rank < CS - 1);

    // Zero both buffers (halos + pad columns) and stage x; init mbarrier.
    for (int i = tid; i < 2 * LROWS * PITCH; i += NTHR) (&bufs[0][0])[i] = 0.f;
    for (int i = tid; i < TSTEPS; i += NTHR) xs[i] = x[batch * TSTEPS + i];
    if (tid == 0) mbar_init(s2u(&mbar), (uint32_t)(nUp + nDn));

    // ---- Per-cell constants (registers): Q, R ----
    const float HM2 = (float)(1.0 / (2.01 * 2.01));
    float Qc[KPT], Rc[KPT], y2[KPT];
#pragma unroll
    for (int k = 0; k < KPT; ++k) {
        const int g = rank * ROWS + rgrp * KPT + k;   // global row
        float cc = rho[g * NG + col];
        float nn = (g > 0)      ? rho[(g - 1) * NG + col] : 0.f;
        float ss = (g < NG - 1) ? rho[(g + 1) * NG + col] : 0.f;
        float ww = (col > 0)    ? rho[g * NG + col - 1]   : 0.f;
        float ee = (col < NG-1) ? rho[g * NG + col + 1]   : 0.f;
        float lpf = 0.5f * cc + 0.125f * (nn + ss + ww + ee);
        float pr  = (1.0f + tanhf(100.0f * (lpf - 0.5f))) * 0.5f;
        float c   = 1.0f - 0.1f * pr;            // C0 + (C1-C0)*pr
        float bx = pml1(g), by = pml1(col);
        float b  = sqrtf(bx * bx + by * by);
        float A1 = 1.0f / (1.0f + 0.5f * b);
        Qc[k] = A1 * (1.0f - 0.5f * b);          // A1*A3 ; A1*A2 = 1 + Qc
        Rc[k] = A1 * (c * c) * HM2;              // A1*c^2/H^2
        y2[k] = 0.f;
    }

    const int base = rgrp * KPT + 1;   // first local data row for this thread
    const float* p0 = &bufs[0][base * PITCH + col + 2];
    const float* p1 = &bufs[1][base * PITCH + col + 2];

    // DSMEM halo-push addresses (top data row -> prev CTA's bottom halo, etc.)
    const bool doUp = nUp && (rgrp == 0);
    const bool doDn = nDn && (rgrp == 3);
    uint32_t upA[2] = {0, 0}, dnA[2] = {0, 0};
    if (doUp) {
        upA[0] = mapa_u32(s2u(&bufs[0][(ROWS + 1) * PITCH + col + 2]), (uint32_t)(rank - 1));
        upA[1] = mapa_u32(s2u(&bufs[1][(ROWS + 1) * PITCH + col + 2]), (uint32_t)(rank - 1));
    }
    if (doDn) {
        dnA[0] = mapa_u32(s2u(&bufs[0][col + 2]), (uint32_t)(rank + 1));
        dnA[1] = mapa_u32(s2u(&bufs[1][col + 2]), (uint32_t)(rank + 1));
    }
    // Remote mbarrier addresses for neighbor arrives (thread 0 only uses these).
    uint32_t mbUp = nUp ? mapa_u32(s2u(&mbar), (uint32_t)(rank - 1)) : 0;
    uint32_t mbDn = nDn ? mapa_u32(s2u(&mbar), (uint32_t)(rank + 1)) : 0;

    // Source (40,96): rank 1, local row 16 -> rgrp 2, k == 4.
    // Probes (160,{48,96,144}): rank 6, local row 16 -> rgrp 2, k == 4.
    const bool isSrc = (rank == 1) && (rgrp == 2) && (col == 96);
    const bool isPrb = (rank == 6) && (rgrp == 2) &&
                       ((col == 48) | (col == 96) | (col == 144));
    float pacc = 0.f;

    cluster_sync_();  // zeros + mbarrier init visible cluster-wide

    for (int t = 0; t < TSTEPS; ++t) {
        const int wb = (t & 1) ^ 1;
        const float* rp = (t & 1) ? p1 : p0;
        float* wp = const_cast<float*>((t & 1) ? p0 : p1);

        float n = rp[-PITCH];
        float c = rp[0];
#pragma unroll
        for (int k = 0; k < KPT; ++k) {
            float s  = rp[(k + 1) * PITCH];
            float wv = rp[k * PITCH - 1];
            float ev = rp[k * PITCH + 1];
            float lap = __fmaf_rn(-4.0f, c, (n + s) + (wv + ev));
            float yn = __fmaf_rn(Rc[k], lap, __fmaf_rn(Qc[k], c - y2[k], c));
            if (k == 4) {
                if (isSrc) yn += xs[t];
            }
            wp[k * PITCH] = yn;
            if (k == 4) {
                if (isPrb) pacc = __fmaf_rn(yn, yn, pacc);
            }
            if (k == 0)       { if (doUp) st_cluster_f32(upA[wb], yn); }
            if (k == KPT - 1) { if (doDn) st_cluster_f32(dnA[wb], yn); }
            y2[k] = c;
            n = c;
            c = s;
        }
        __syncthreads();  // orders intra-CTA writes + halo pushes before arrive
        if (tid == 0) {
            if (nUp) mbar_arrive_remote(mbUp);
            if (nDn) mbar_arrive_remote(mbDn);
        }
        mbar_wait_parity_cluster(s2u(&mbar), (uint32_t)(t & 1));
    }

    cluster_sync_();  // quiesce in-flight DSMEM traffic before any CTA exits

    if (isPrb) pbuf[(col - 48) / 48] = pacc;
    __syncthreads();
    if (rank == 6 && tid == 0) {
        float a = pbuf[0], b = pbuf[1], cc = pbuf[2];
        float sum = a + b + cc;
        out[batch * 3 + 0] = a / sum;
        out[batch * 3 + 1] = b / sum;
        out[batch * 3 + 2] = cc / sum;
    }
}

extern "C" void kernel_launch(void* const* d_in, const int* in_sizes, int n_in,
                              void* d_out, int out_size)
{
    (void)in_sizes; (void)n_in; (void)out_size;
    const float* x   = (const float*)d_in[0];   // (4,256) f32
    const float* rho = (const float*)d_in[1];   // (192,192) f32
    float* out = (float*)d_out;                 // (4,3) f32
    wave_kernel<<<dim3(CS * 4), dim3(NTHR)>>>(x, rho, out);
}

// round 3
// speedup vs baseline: 1.1233x; 1.1233x over previous
#include <cuda_runtime.h>
#include <cstdint>
#include <math.h>

#define CS     8
#define ROWS   24
#define NG     192
#define TSTEPS 256
#define NTHR   384
#define KPT    12

__device__ __forceinline__ uint32_t s2u(const void* p) {
    return (uint32_t)__cvta_generic_to_shared((void*)p);
}
__device__ __forceinline__ uint32_t mapa_u32(uint32_t a, uint32_t r) {
    uint32_t d;
    asm("mapa.shared::cluster.u32 %0, %1, %2;" : "=r"(d) : "r"(a), "r"(r));
    return d;
}
__device__ __forceinline__ void st_cluster_f32(uint32_t a, float v) {
    asm volatile("st.shared::cluster.f32 [%0], %1;" :: "r"(a), "f"(v) : "memory");
}
__device__ __forceinline__ void cl_arrive() {
    asm volatile("barrier.cluster.arrive.aligned;" ::: "memory");
}
__device__ __forceinline__ void cl_wait() {
    asm volatile("barrier.cluster.wait.aligned;" ::: "memory");
}

// PML 1D profile: v[k] = 3*(k/20)^4
__device__ __forceinline__ float pml1(int i) {
    int d;
    if (i <= 20)           d = 20 - i;
    else if (i >= NG - 21) d = i - (NG - 21);
    else return 0.0f;
    double t = (double)d * 0.05;
    double t2 = t * t;
    return (float)(3.0 * t2 * t2);
}

__global__ void __cluster_dims__(CS, 1, 1) __launch_bounds__(NTHR, 1)
wave_kernel(const float* __restrict__ x, const float* __restrict__ rho,
            float* __restrict__ out)
{
    // Boundary-exchange buffers, double-buffered by step parity.
    __shared__ float bufL[2][2][7][KPT];   // value at col 32*cw (lane0 writes idx cw); idx 6 = 0 guard
    __shared__ float bufR[2][2][7][KPT];   // value at col 32*cw+31 (lane31 writes idx cw+1); idx 0 = 0 guard
    __shared__ float rowbuf[2][2][NG];     // [p][0] = local row 11 (rgrp0 pub), [p][1] = local row 12 (rgrp1 pub)
    __shared__ float halo[2][2][NG];       // [p][0] = haloTop (row -1, DSMEM), [p][1] = haloBot (row 24)
    __shared__ float xs[TSTEPS];
    __shared__ float pbuf[3];

    const int tid  = threadIdx.x;
    const int col  = tid % NG;
    const int rgrp = tid / NG;             // 0 or 1 (rows 0-11 / 12-23)
    const int lane = tid & 31;
    const int cw   = col >> 5;             // 0..5
    const int rank = blockIdx.x % CS;
    const int batch= blockIdx.x / CS;

    // zero smem
    for (int i = tid; i < 2*2*7*KPT; i += NTHR) { (&bufL[0][0][0][0])[i] = 0.f; (&bufR[0][0][0][0])[i] = 0.f; }
    for (int i = tid; i < 2*2*NG;    i += NTHR) { (&rowbuf[0][0][0])[i] = 0.f; (&halo[0][0][0])[i] = 0.f; }
    for (int i = tid; i < TSTEPS;    i += NTHR) xs[i] = x[batch * TSTEPS + i];

    // ---- Per-cell coefficients: yn = Qp*c - Qm*y2 + Rc*(n+s+w+e) ----
    const float HM2 = (float)(1.0 / (2.01 * 2.01));
    float ya[KPT], yb[KPT], Qp[KPT], Qm[KPT], Rc[KPT];
#pragma unroll
    for (int k = 0; k < KPT; ++k) {
        int g = rank * ROWS + rgrp * KPT + k;
        float cc = rho[g * NG + col];
        float nn = (g > 0)      ? rho[(g - 1) * NG + col] : 0.f;
        float ss = (g < NG - 1) ? rho[(g + 1) * NG + col] : 0.f;
        float ww = (col > 0)    ? rho[g * NG + col - 1]   : 0.f;
        float ee = (col < NG-1) ? rho[g * NG + col + 1]   : 0.f;
        float lpf = 0.5f * cc + 0.125f * (nn + ss + ww + ee);
        float pr  = (1.0f + tanhf(100.0f * (lpf - 0.5f))) * 0.5f;
        float c   = 1.0f - 0.1f * pr;
        float bx = pml1(g), by = pml1(col);
        float bb = sqrtf(bx * bx + by * by);
        float A1 = 1.0f / (1.0f + 0.5f * bb);
        float Q  = A1 * (1.0f - 0.5f * bb);
        float R  = A1 * (c * c) * HM2;
        Rc[k] = R; Qm[k] = Q; Qp[k] = 1.0f + Q - 4.0f * R;
        ya[k] = 0.f; yb[k] = 0.f;
    }

    const bool isL = (lane == 0), isR = (lane == 31), isEdge = isL | isR;
    const float* eRead[2]; float* eWrite[2];
#pragma unroll
    for (int p = 0; p < 2; ++p) {
        eRead[p]  = isL ? &bufR[p][rgrp][cw][0]     : &bufL[p][rgrp][cw + 1][0];
        eWrite[p] = isL ? &bufL[p][rgrp][cw][0]     : &bufR[p][rgrp][cw + 1][0];
    }
    const float* nTop[2]; const float* sBot[2]; float* rowPub[2];
#pragma unroll
    for (int p = 0; p < 2; ++p) {
        nTop[p]   = (rgrp == 0) ? &halo[p][0][col]   : &rowbuf[p][0][col];
        sBot[p]   = (rgrp == 1) ? &halo[p][1][col]   : &rowbuf[p][1][col];
        rowPub[p] = (rgrp == 0) ? &rowbuf[p][0][col] : &rowbuf[p][1][col];
    }
    const bool doPush = (rgrp == 0) ? (rank > 0) : (rank < CS - 1);
    uint32_t pushA[2];
    {
        int nr = (rgrp == 0) ? max(rank - 1, 0) : min(rank + 1, CS - 1);
#pragma unroll
        for (int p = 0; p < 2; ++p) {
            uint32_t la = (rgrp == 0) ? s2u(&halo[p][1][col]) : s2u(&halo[p][0][col]);
            pushA[p] = mapa_u32(la, (uint32_t)nr);
        }
    }

    // Source (40,96): rank 1, local row 16 -> rgrp 1, k=4. Probes (160,{48,96,144}): rank 6, rgrp 1, k=4.
    const bool isSrc = (rank == 1) && (rgrp == 1) && (col == 96);
    const bool isPrb = (rank == 6) && (rgrp == 1) &&
                       ((col == 48) | (col == 96) | (col == 144));
    float pacc = 0.f;

    cl_arrive(); cl_wait();   // zeros + setup visible cluster-wide

    // One step: cur = state t (regs), nw = state t-1 on entry (y2), overwritten with state t+1.
    auto stepf = [&](float (&cur)[KPT], float (&nw)[KPT],
                     const float* nT, const float* sB, float* rP,
                     const float* eR, float* eW, uint32_t pA, int t) {
        // ---- phase 1: boundary rows k=0 and k=KPT-1, halo push, arrive ----
        float c0 = cur[0];
        float w0 = __shfl_up_sync(0xffffffffu, c0, 1);
        float e0 = __shfl_down_sync(0xffffffffu, c0, 1);
        if (isEdge) { float pv = eR[0]; if (isL) w0 = pv; else e0 = pv; }
        float yn0 = fmaf(Qp[0], c0,
                    fmaf(-Qm[0], nw[0], Rc[0] * ((*nT + cur[1]) + (w0 + e0))));

        float c1 = cur[KPT - 1];
        float w1 = __shfl_up_sync(0xffffffffu, c1, 1);
        float e1 = __shfl_down_sync(0xffffffffu, c1, 1);
        if (isEdge) { float pv = eR[KPT - 1]; if (isL) w1 = pv; else e1 = pv; }
        float yn1 = fmaf(Qp[KPT - 1], c1,
                    fmaf(-Qm[KPT - 1], nw[KPT - 1],
                         Rc[KPT - 1] * ((cur[KPT - 2] + *sB) + (w1 + e1))));

        nw[0] = yn0; nw[KPT - 1] = yn1;
        if (doPush) st_cluster_f32(pA, (rgrp == 0) ? yn0 : yn1);
        cl_arrive();                       // releases the DSMEM halo push

        if (isEdge) { eW[0] = yn0; eW[KPT - 1] = yn1; }
        *rP = (rgrp == 0) ? yn1 : yn0;

        // ---- phase 2: interior rows, overlapping the cluster barrier ----
#pragma unroll
        for (int k = 1; k < KPT - 1; ++k) {
            float c  = cur[k];
            float wv = __shfl_up_sync(0xffffffffu, c, 1);
            float ev = __shfl_down_sync(0xffffffffu, c, 1);
            if (isEdge) { float pv = eR[k]; if (isL) wv = pv; else ev = pv; }
            float yn = fmaf(Qp[k], c,
                       fmaf(-Qm[k], nw[k], Rc[k] * ((cur[k - 1] + cur[k + 1]) + (wv + ev))));
            if (k == 4) {
                if (isSrc) yn += xs[t];
                if (isPrb) pacc = fmaf(yn, yn, pacc);
            }
            nw[k] = yn;
            if (isEdge) eW[k] = yn;
        }
        __syncthreads();                   // intra-CTA colbuf/rowbuf visibility
        cl_wait();                         // acquires peers' halo pushes
    };

    for (int t = 0; t < TSTEPS; t += 2) {
        // even step: state t in ya (parity 0 buffers), write parity 1
        stepf(ya, yb, nTop[0], sBot[0], rowPub[1], eRead[0], eWrite[1], pushA[1], t);
        // odd step: state t+1 in yb (parity 1 buffers), write parity 0
        stepf(yb, ya, nTop[1], sBot[1], rowPub[0], eRead[0 + 1], eWrite[0], pushA[0], t + 1);
    }

    if (isPrb) pbuf[(col - 48) / 48] = pacc;
    __syncthreads();
    if (rank == 6 && tid == 0) {
        float a = pbuf[0], b = pbuf[1], c = pbuf[2];
        float s = a + b + c;
        out[batch * 3 + 0] = a / s;
        out[batch * 3 + 1] = b / s;
        out[batch * 3 + 2] = c / s;
    }
}

extern "C" void kernel_launch(void* const* d_in, const int* in_sizes, int n_in,
                              void* d_out, int out_size)
{
    (void)in_sizes; (void)n_in; (void)out_size;
    const float* x   = (const float*)d_in[0];   // (4,256) f32
    const float* rho = (const float*)d_in[1];   // (192,192) f32
    float* out = (float*)d_out;                 // (4,3) f32
    wave_kernel<<<dim3(CS * 4), dim3(NTHR)>>>(x, rho, out);
}